// round 15
// baseline (speedup 1.0000x reference)
#include <cuda_runtime.h>
#include <math.h>
#include <stdint.h>

// ---------------------------------------------------------------------------
// GRUEncoder: B=256, T=512, IN_DIM=75, H=256, 2-layer GRU + FC
//   K0: xg0 = x @ W_ih0^T + b_ih0
//   K1: layer0 recurrence (8-CTA clusters, occ 2, shuffle-reduce, st.async)
//   K2: xg1 = out0 @ W_ih1^T + b_ih1
//   K3: layer1 recurrence -> hT
//   K4: emb = hT @ fc_W^T + fc_b
// Recurrence: cluster of 8 CTAs x 32 units, 8 rows/cluster, TWO co-resident
// CTAs per SM (independent clusters) hide each other's serial tails.
// Cross-k reduce via warp butterfly shuffles -> zero smem, no __syncthreads
// in the time loop.
// ---------------------------------------------------------------------------

#define B_  256
#define T_  512
#define H_  256
#define G3_ 768
#define INDIM_ 75

__device__ float g_xg[(size_t)B_ * T_ * G3_];
__device__ float g_out0[(size_t)B_ * T_ * H_];
__device__ float g_hT[(size_t)B_ * H_];

typedef unsigned long long u64;

__device__ __forceinline__ u64 pack2(float lo, float hi) {
    u64 d; asm("mov.b64 %0, {%1, %2};" : "=l"(d) : "f"(lo), "f"(hi)); return d;
}
__device__ __forceinline__ void unpack2(u64 v, float& lo, float& hi) {
    asm("mov.b64 {%0, %1}, %2;" : "=f"(lo), "=f"(hi) : "l"(v));
}
__device__ __forceinline__ u64 ffma2(u64 a, u64 b, u64 c) {
    u64 d; asm("fma.rn.f32x2 %0, %1, %2, %3;" : "=l"(d) : "l"(a), "l"(b), "l"(c)); return d;
}
__device__ __forceinline__ uint32_t smem_u32(const void* p) {
    uint32_t a;
    asm("{ .reg .u64 t; cvta.to.shared.u64 t, %1; cvt.u32.u64 %0, t; }" : "=r"(a) : "l"(p));
    return a;
}
__device__ __forceinline__ uint32_t mapa_(uint32_t addr, uint32_t rank) {
    uint32_t r; asm("mapa.shared::cluster.u32 %0, %1, %2;" : "=r"(r) : "r"(addr), "r"(rank));
    return r;
}
__device__ __forceinline__ uint32_t ctarank_() {
    uint32_t r; asm("mov.u32 %0, %%cluster_ctarank;" : "=r"(r)); return r;
}
#define CLUSTER_BAR() do { \
    asm volatile("barrier.cluster.arrive.aligned;" ::: "memory"); \
    asm volatile("barrier.cluster.wait.aligned;"   ::: "memory"); } while (0)

__device__ __forceinline__ void mbar_init(uint32_t addr, uint32_t cnt) {
    asm volatile("mbarrier.init.shared.b64 [%0], %1;" :: "r"(addr), "r"(cnt) : "memory");
}
__device__ __forceinline__ void mbar_expect_tx(uint32_t addr, uint32_t bytes) {
    asm volatile("mbarrier.arrive.expect_tx.shared.b64 _, [%0], %1;"
                 :: "r"(addr), "r"(bytes) : "memory");
}
__device__ __forceinline__ void st_async_u64(uint32_t raddr, u64 v, uint32_t rmbar) {
    asm volatile("st.async.shared::cluster.mbarrier::complete_tx::bytes.b64 [%0], %1, [%2];"
                 :: "r"(raddr), "l"(v), "r"(rmbar) : "memory");
}
__device__ __forceinline__ void mbar_wait_parity(uint32_t addr, uint32_t parity) {
    uint32_t done;
    asm volatile(
        "{\n\t.reg .pred p;\n\t"
        "mbarrier.try_wait.parity.acquire.cluster.shared::cta.b64 p, [%1], %2;\n\t"
        "selp.b32 %0, 1, 0, p;\n\t}"
        : "=r"(done) : "r"(addr), "r"(parity) : "memory");
    if (!done) {
        asm volatile(
            "{\n\t.reg .pred P1;\n\t"
            "WL_%=:\n\t"
            "mbarrier.try_wait.parity.acquire.cluster.shared::cta.b64 P1, [%0], %1, 0x989680;\n\t"
            "@P1 bra.uni WD_%=;\n\t"
            "bra.uni WL_%=;\n\t"
            "WD_%=:\n\t}"
            :: "r"(addr), "r"(parity) : "memory");
    }
}

__device__ __forceinline__ float sigm(float x)  { return __fdividef(1.f, 1.f + __expf(-x)); }
__device__ __forceinline__ float tanhf_(float x){ return __fdividef(2.f, 1.f + __expf(-2.f * x)) - 1.f; }

// ---------------------------------------------------------------------------
// Tiled GEMM: C[M,N] = A[M,K] @ B[N,K]^T + bias[N]   (unchanged, known-good)
// ---------------------------------------------------------------------------
__global__ __launch_bounds__(256)
void gemm_bias_kernel(const float* __restrict__ A, const float* __restrict__ Bm,
                      const float* __restrict__ bias, float* __restrict__ C,
                      int M, int N, int K)
{
    __shared__ __align__(16) float As[8][132];
    __shared__ __align__(16) float Bs[8][68];

    const int tx = threadIdx.x & 15;
    const int ty = threadIdx.x >> 4;
    const int m0 = blockIdx.y * 128;
    const int n0 = blockIdx.x * 64;

    u64 acc[4][4];
#pragma unroll
    for (int p = 0; p < 4; p++)
#pragma unroll
        for (int c = 0; c < 4; c++) acc[p][c] = 0ull;

    for (int k0 = 0; k0 < K; k0 += 8) {
#pragma unroll
        for (int i = 0; i < 4; i++) {
            int idx = threadIdx.x + i * 256;
            int m = idx >> 3, k = idx & 7;
            float v = 0.0f;
            if (k0 + k < K) v = A[(size_t)(m0 + m) * K + (k0 + k)];
            As[k][m] = v;
        }
#pragma unroll
        for (int i = 0; i < 2; i++) {
            int idx = threadIdx.x + i * 256;
            int n = idx >> 3, k = idx & 7;
            float v = 0.0f;
            if (k0 + k < K) v = Bm[(size_t)(n0 + n) * K + (k0 + k)];
            Bs[k][n] = v;
        }
        __syncthreads();

#pragma unroll
        for (int k = 0; k < 8; k++) {
            float4 a0 = *(const float4*)&As[k][ty * 8];
            float4 a1 = *(const float4*)&As[k][ty * 8 + 4];
            float4 b  = *(const float4*)&Bs[k][tx * 4];
            u64 ap[4] = { pack2(a0.x, a0.y), pack2(a0.z, a0.w),
                          pack2(a1.x, a1.y), pack2(a1.z, a1.w) };
            u64 bb[4] = { pack2(b.x, b.x), pack2(b.y, b.y),
                          pack2(b.z, b.z), pack2(b.w, b.w) };
#pragma unroll
            for (int p = 0; p < 4; p++)
#pragma unroll
                for (int c = 0; c < 4; c++)
                    acc[p][c] = ffma2(ap[p], bb[c], acc[p][c]);
        }
        __syncthreads();
    }

    float bv[4];
#pragma unroll
    for (int c = 0; c < 4; c++) bv[c] = bias[n0 + tx * 4 + c];

#pragma unroll
    for (int p = 0; p < 4; p++) {
        float lo[4], hi[4];
#pragma unroll
        for (int c = 0; c < 4; c++) unpack2(acc[p][c], lo[c], hi[c]);
        int r0 = m0 + ty * 8 + 2 * p;
        float4 o0 = make_float4(lo[0] + bv[0], lo[1] + bv[1], lo[2] + bv[2], lo[3] + bv[3]);
        float4 o1 = make_float4(hi[0] + bv[0], hi[1] + bv[1], hi[2] + bv[2], hi[3] + bv[3]);
        *(float4*)&C[(size_t)r0 * N + n0 + tx * 4]       = o0;
        *(float4*)&C[(size_t)(r0 + 1) * N + n0 + tx * 4] = o1;
    }
}

// ---------------------------------------------------------------------------
// 8-CTA cluster GRU recurrence, occupancy 2.
// 32 clusters x 8 CTAs = 256 CTAs, 2 per SM. Cluster owns 8 batch rows;
// CTA rank c owns units [32c, 32c+32).
// Thread (w in [0,8), lane l): unit = 4w + (l&3), k-slice s = l>>2 covers
// k in [32s, 32s+32) (u64 k-pairs kp = 16s + i, i in [0,16)).
// Per step: GEMM (384 FFMA2/thread: 16 kp x 8 rows x 3 gates) ->
// butterfly shuffle reduce over s (21 SHFL) -> lane finalizes (unit, row=s)
// -> even lanes pack unit-pairs and st.async.b64 to all 8 CTAs.
// One mbarrier per CTA, tx = 8192 B (all 8 sources x 128 stores x 8B).
// SMEM layouts (bank-engineered):
//   Ws2[i][w][q=4s+m][3 gates] u64: bank-pair = (3q+g)%16 -> uniform 2-way
//     (= the 256B/128B data minimum for 32 distinct u64).
//   hb[par][i][rowpair][slice][rowhalf] u64: LDS.128 bank-quad = 4*s,
//     conflict-free; producers write (unit-pair, row) slots via st.async.
// SMEM total: 98304 + 16384 + 64 = 114752 B -> two CTAs/SM fit in 228KB.
// ---------------------------------------------------------------------------
#define HB_OFF    98304
#define MB_OFF    114688
#define GRU_SMEM  114752

template<bool WRITE_OUT, bool WRITE_HT>
__global__ void __cluster_dims__(8, 1, 1) __launch_bounds__(256, 2)
gru_cluster_kernel(const float* __restrict__ xg, const float* __restrict__ Whh,
                   const float* __restrict__ bhh,
                   float* __restrict__ out, float* __restrict__ hT)
{
    extern __shared__ __align__(16) char smem[];
    u64* Ws2 = (u64*)smem;                    // [16 i][8 w][32 q][3 g] = 12288 u64
    u64* hb  = (u64*)(smem + HB_OFF);         // [2 par][16 i][4 rp][8 sl][2 rh] = 2048 u64
    u64* mbs = (u64*)(smem + MB_OFF);

    const int tid = threadIdx.x;
    const int w   = tid >> 5;
    const int l   = tid & 31;
    const int m   = l & 3;
    const int s   = l >> 2;
    const uint32_t crank = ctarank_();
    const int uglob = 32 * (int)crank + 4 * w + m;
    const int row   = (blockIdx.x >> 3) * 8 + s;

    // ---- stage W_hh into the banked layout ----
    for (int idx = tid; idx < 12288; idx += 256) {
        int g  = idx % 3;
        int q  = (idx / 3) & 31;
        int w_ = (idx / 96) & 7;
        int i  = idx / 768;
        int kp = 16 * (q >> 2) + i;
        int grow = g * 256 + 32 * (int)crank + 4 * w_ + (q & 3);
        float2 v = ((const float2*)Whh)[(size_t)grow * 128 + kp];
        Ws2[idx] = pack2(v.x, v.y);
    }
    for (int i2 = tid; i2 < 2048; i2 += 256) hb[i2] = 0ull;
    if (tid == 0) mbar_init(smem_u32(&mbs[0]), 1);
    __syncthreads();
    CLUSTER_BAR();   // weights, h zeros, mbarrier visible cluster-wide

    const float br = bhh[uglob], bz = bhh[256 + uglob], bn = bhh[512 + uglob];
    const uint32_t mlocal = smem_u32(&mbs[0]);

    // producer slot (parity 0): unit-pair kp_u = uglob>>1 -> i = 2w + (m>>1),
    // slice-dim = crank, rowpair = s>>1, rowhalf = s&1. Even-m lanes store.
    uint32_t stslot = smem_u32(
        &hb[(size_t)(((2 * w + (m >> 1)) * 4 + (s >> 1)) * 8 + (int)crank) * 2 + (s & 1)]);
    uint32_t haddr[8], maddr[8];
#pragma unroll
    for (int i = 0; i < 8; i++) {
        uint32_t rk = (crank + i) & 7;
        haddr[i] = mapa_(stslot, rk);
        maddr[i] = mapa_(mlocal, rk);
    }

    const float* px = xg + ((size_t)row * T_) * G3_ + uglob;
    float* po = WRITE_OUT ? out + ((size_t)row * T_) * H_ + uglob : nullptr;

    float hp = 0.f;

    for (int t = 0; t < T_; t++) {
        // xg prefetch (independent of h(t)) — in flight across the wait+GEMM
        float xr = px[0], xz = px[256], xn = px[512];

        if (t > 0) mbar_wait_parity(mlocal, (uint32_t)((t - 1) & 1));
        if (tid == 0 && t < T_ - 1) mbar_expect_tx(mlocal, 8192);

        // GEMM: 16 kp iters x 8 rows x 3 gates, f32x2 lanes = (even k, odd k)
        u64 acc[3][8];
#pragma unroll
        for (int g = 0; g < 3; g++)
#pragma unroll
            for (int r = 0; r < 8; r++) acc[g][r] = 0ull;
        {
            const u64* wp = Ws2 + (size_t)(w * 32 + 4 * s + m) * 3;
            const u64* hk = hb + (size_t)(t & 1) * 1024 + s * 2;
#pragma unroll 4
            for (int i = 0; i < 16; i++) {
                u64 wr = wp[0], wz2 = wp[1], wn2 = wp[2];
                ulonglong2 h01 = *(const ulonglong2*)(hk);
                ulonglong2 h23 = *(const ulonglong2*)(hk + 16);
                ulonglong2 h45 = *(const ulonglong2*)(hk + 32);
                ulonglong2 h67 = *(const ulonglong2*)(hk + 48);
                acc[0][0] = ffma2(h01.x, wr, acc[0][0]);
                acc[0][1] = ffma2(h01.y, wr, acc[0][1]);
                acc[0][2] = ffma2(h23.x, wr, acc[0][2]);
                acc[0][3] = ffma2(h23.y, wr, acc[0][3]);
                acc[0][4] = ffma2(h45.x, wr, acc[0][4]);
                acc[0][5] = ffma2(h45.y, wr, acc[0][5]);
                acc[0][6] = ffma2(h67.x, wr, acc[0][6]);
                acc[0][7] = ffma2(h67.y, wr, acc[0][7]);
                acc[1][0] = ffma2(h01.x, wz2, acc[1][0]);
                acc[1][1] = ffma2(h01.y, wz2, acc[1][1]);
                acc[1][2] = ffma2(h23.x, wz2, acc[1][2]);
                acc[1][3] = ffma2(h23.y, wz2, acc[1][3]);
                acc[1][4] = ffma2(h45.x, wz2, acc[1][4]);
                acc[1][5] = ffma2(h45.y, wz2, acc[1][5]);
                acc[1][6] = ffma2(h67.x, wz2, acc[1][6]);
                acc[1][7] = ffma2(h67.y, wz2, acc[1][7]);
                acc[2][0] = ffma2(h01.x, wn2, acc[2][0]);
                acc[2][1] = ffma2(h01.y, wn2, acc[2][1]);
                acc[2][2] = ffma2(h23.x, wn2, acc[2][2]);
                acc[2][3] = ffma2(h23.y, wn2, acc[2][3]);
                acc[2][4] = ffma2(h45.x, wn2, acc[2][4]);
                acc[2][5] = ffma2(h45.y, wn2, acc[2][5]);
                acc[2][6] = ffma2(h67.x, wn2, acc[2][6]);
                acc[2][7] = ffma2(h67.y, wn2, acc[2][7]);
                wp += 768; hk += 64;
            }
        }

        // scalarize (even+odd k halves)
        float cur[3][8];
#pragma unroll
        for (int g = 0; g < 3; g++)
#pragma unroll
            for (int r = 0; r < 8; r++) {
                float lo, hi; unpack2(acc[g][r], lo, hi); cur[g][r] = lo + hi;
            }

        // butterfly fold over the 8 k-slices (lane bits 4,3,2 = s bits 2,1,0);
        // lane ends holding the full pre-activation for (unit, row = s).
        const bool b2 = (l & 16) != 0;
        float n1[3][4];
#pragma unroll
        for (int g = 0; g < 3; g++)
#pragma unroll
            for (int j = 0; j < 4; j++) {
                float snd = b2 ? cur[g][j] : cur[g][4 + j];
                float rcv = __shfl_xor_sync(0xffffffffu, snd, 16);
                n1[g][j] = (b2 ? cur[g][4 + j] : cur[g][j]) + rcv;
            }
        const bool b1 = (l & 8) != 0;
        float n2[3][2];
#pragma unroll
        for (int g = 0; g < 3; g++)
#pragma unroll
            for (int j = 0; j < 2; j++) {
                float snd = b1 ? n1[g][j] : n1[g][2 + j];
                float rcv = __shfl_xor_sync(0xffffffffu, snd, 8);
                n2[g][j] = (b1 ? n1[g][2 + j] : n1[g][j]) + rcv;
            }
        const bool b0 = (l & 4) != 0;
        float pre[3];
#pragma unroll
        for (int g = 0; g < 3; g++) {
            float snd = b0 ? n2[g][0] : n2[g][1];
            float rcv = __shfl_xor_sync(0xffffffffu, snd, 4);
            pre[g] = (b0 ? n2[g][1] : n2[g][0]) + rcv;
        }

        float r = sigm(xr + pre[0] + br);
        float z = sigm(xz + pre[1] + bz);
        float n = tanhf_(xn + r * (pre[2] + bn));
        float h = n + z * (hp - n);

        if (WRITE_OUT) { po[0] = h; po += H_; }

        if (t < T_ - 1) {
            // even lane packs (its unit, right neighbor's unit) -> one b64
            float hnb = __shfl_down_sync(0xffffffffu, h, 1);
            if ((m & 1) == 0) {
                u64 hv = pack2(h, hnb);
                uint32_t poff = (uint32_t)((t + 1) & 1) * 8192u;
#pragma unroll
                for (int i = 0; i < 8; i++)
                    st_async_u64(haddr[i] + poff, hv, maddr[i]);
            }
        }

        hp = h;
        px += G3_;
    }

    if (WRITE_HT) hT[(size_t)row * H_ + uglob] = hp;
    CLUSTER_BAR();   // no CTA exits with peers' remote accesses in flight
}

// ---------------------------------------------------------------------------
extern "C" void kernel_launch(void* const* d_in, const int* in_sizes, int n_in,
                              void* d_out, int out_size)
{
    const float* x     = (const float*)d_in[0];
    const float* W_ih0 = (const float*)d_in[1];
    const float* W_hh0 = (const float*)d_in[2];
    const float* b_ih0 = (const float*)d_in[3];
    const float* b_hh0 = (const float*)d_in[4];
    const float* W_ih1 = (const float*)d_in[5];
    const float* W_hh1 = (const float*)d_in[6];
    const float* b_ih1 = (const float*)d_in[7];
    const float* b_hh1 = (const float*)d_in[8];
    const float* fc_W  = (const float*)d_in[9];
    const float* fc_b  = (const float*)d_in[10];
    float* out = (float*)d_out;

    float *xg, *out0, *hT;
    cudaGetSymbolAddress((void**)&xg,   g_xg);
    cudaGetSymbolAddress((void**)&out0, g_out0);
    cudaGetSymbolAddress((void**)&hT,   g_hT);

    cudaFuncSetAttribute(gru_cluster_kernel<true,  false>,
                         cudaFuncAttributeMaxDynamicSharedMemorySize, GRU_SMEM);
    cudaFuncSetAttribute(gru_cluster_kernel<false, true>,
                         cudaFuncAttributeMaxDynamicSharedMemorySize, GRU_SMEM);

    const int MT = B_ * T_;

    gemm_bias_kernel<<<dim3(G3_ / 64, MT / 128), 256>>>(x, W_ih0, b_ih0, xg, MT, G3_, INDIM_);
    gru_cluster_kernel<true,  false><<<256, 256, GRU_SMEM>>>(xg, W_hh0, b_hh0, out0, nullptr);
    gemm_bias_kernel<<<dim3(G3_ / 64, MT / 128), 256>>>(out0, W_ih1, b_ih1, xg, MT, G3_, H_);
    gru_cluster_kernel<false, true><<<256, 256, GRU_SMEM>>>(xg, W_hh1, b_hh1, nullptr, hT);
    gemm_bias_kernel<<<dim3(H_ / 64, B_ / 128), 256>>>(hT, fc_W, fc_b, out, B_, H_, H_);
}